// round 3
// baseline (speedup 1.0000x reference)
#include <cuda_runtime.h>
#include <math.h>

// Problem constants
#define BATCH 16
#define SEQ 512
#define DM 1024
#define NH 16
#define HD 64
#define NTOK (BATCH * SEQ)   // 8192

// ---------------- scratch (allocation-free: __device__ globals) ----------------
__device__ float g_q[NTOK * DM];
__device__ float g_k[NTOK * DM];
__device__ float g_v[NTOK * DM];
__device__ float g_ctx[NTOK * DM];

// ---------------- classic 32x32 tiled GEMM ------------------------------------
// C[m,n] = sum_k A[m,k] * W[n,k] + bias[n]
// dst_sel: 0->g_q, 1->g_k, 2->g_v, 3->Cout(param)
// src_sel: 0->Ain(param), 1->g_ctx
__global__ __launch_bounds__(1024) void gemm32(
    const float* __restrict__ Ain, const float* __restrict__ W,
    const float* __restrict__ bias, float* Cout,
    int dst_sel, int src_sel)
{
    const float* A = (src_sel == 0) ? Ain : g_ctx;
    float* C = (dst_sel == 0) ? g_q
             : (dst_sel == 1) ? g_k
             : (dst_sel == 2) ? g_v
             : Cout;

    __shared__ float As[32][33];
    __shared__ float Ws[32][33];

    const int tx = threadIdx.x;   // 0..31
    const int ty = threadIdx.y;   // 0..31
    const int m = blockIdx.y * 32 + ty;
    const int n = blockIdx.x * 32 + tx;

    float acc = 0.f;
    for (int k0 = 0; k0 < DM; k0 += 32) {
        As[ty][tx] = A[(size_t)m * DM + k0 + tx];                         // coalesced
        Ws[ty][tx] = W[(size_t)(blockIdx.x * 32 + ty) * DM + k0 + tx];    // coalesced
        __syncthreads();
        #pragma unroll
        for (int kk = 0; kk < 32; kk++)
            acc += As[ty][kk] * Ws[tx][kk];
        __syncthreads();
    }
    C[(size_t)m * DM + n] = acc + bias[n];
}

// ---------------- RoPE (literal transliteration of the reference) -------------
// inv_freq[i] = 1 / 10000^(2i/64), i = 0..31
// angle = pos * inv_freq[i]
// out[i]    = x[i]*cos - x[i+32]*sin
// out[i+32] = x[i+32]*cos + x[i]*sin        (applied per head, in place)
__global__ __launch_bounds__(512) void rope_naive()
{
    const int token = blockIdx.x;            // 0..8191
    const int pos = token & (SEQ - 1);       // position within sequence
    const int h = threadIdx.x >> 5;          // 0..15
    const int i = threadIdx.x & 31;          // 0..31 pair index

    const float expo = (float)(2 * i) / 64.0f;
    const float invf = 1.0f / powf(10000.0f, expo);
    const float ang = (float)pos * invf;
    const float c = cosf(ang);
    const float s = sinf(ang);

    const size_t base = (size_t)token * DM + h * HD;
    float a = g_q[base + i], b = g_q[base + i + 32];
    g_q[base + i]      = a * c - b * s;
    g_q[base + i + 32] = b * c + a * s;
    a = g_k[base + i];  b = g_k[base + i + 32];
    g_k[base + i]      = a * c - b * s;
    g_k[base + i + 32] = b * c + a * s;
}

// ---------------- naive attention: one block per (b, h, q) --------------------
// Full 512-wide softmax (no online softmax), smem tree reductions.
__global__ __launch_bounds__(256) void attn_naive()
{
    __shared__ float qrow[HD];
    __shared__ float p[SEQ];
    __shared__ float red[256];

    const int qpos = blockIdx.x;   // 0..511
    const int h = blockIdx.y;      // 0..15
    const int b = blockIdx.z;      // 0..15
    const int tid = threadIdx.x;   // 0..255
    const size_t base = (size_t)b * SEQ * DM + (size_t)h * HD;

    // load q row (64 floats)
    if (tid < HD) qrow[tid] = g_q[base + (size_t)qpos * DM + tid];
    __syncthreads();

    // scores: thread handles k = tid and k = tid + 256
    for (int k = tid; k < SEQ; k += 256) {
        const float* kr = &g_k[base + (size_t)k * DM];
        float s = 0.f;
        for (int d = 0; d < HD; d++)
            s += qrow[d] * kr[d];
        p[k] = s * 0.125f;    // scale = 1/sqrt(64)
    }
    __syncthreads();

    // max reduction
    red[tid] = fmaxf(p[tid], p[tid + 256]);
    __syncthreads();
    for (int off = 128; off > 0; off >>= 1) {
        if (tid < off) red[tid] = fmaxf(red[tid], red[tid + off]);
        __syncthreads();
    }
    const float mx = red[0];
    __syncthreads();   // everyone has read red[0] before reuse

    // exp + sum reduction
    const float e0 = expf(p[tid] - mx);
    const float e1 = expf(p[tid + 256] - mx);
    p[tid] = e0;
    p[tid + 256] = e1;
    red[tid] = e0 + e1;
    __syncthreads();
    for (int off = 128; off > 0; off >>= 1) {
        if (tid < off) red[tid] += red[tid + off];
        __syncthreads();
    }
    const float inv = 1.0f / red[0];
    __syncthreads();   // everyone has read red[0] before reuse

    // out[d] = inv * sum_k p[k] * V[k][d]
    // 256 threads: d = tid & 63, k-quarter = tid >> 6 (128 k each), then reduce 4 partials
    {
        const int d = tid & 63;
        const int kq = tid >> 6;
        float acc = 0.f;
        for (int k = kq * 128; k < kq * 128 + 128; k++)
            acc += p[k] * g_v[base + (size_t)k * DM + d];
        red[tid] = acc;
    }
    __syncthreads();
    if (tid < HD) {
        const float r = red[tid] + red[tid + 64] + red[tid + 128] + red[tid + 192];
        g_ctx[(size_t)(b * SEQ + qpos) * DM + h * HD + tid] = r * inv;
    }
}

// ---------------- launch -------------------------------------------------------
extern "C" void kernel_launch(void* const* d_in, const int* in_sizes, int n_in,
                              void* d_out, int out_size)
{
    // classify inputs by size (identity under dict order:
    // query,key,value, Wq,bq, Wk,bk, Wv,bv, Wo,bo)
    const float* act[3] = {0, 0, 0};
    const float* wgt[4] = {0, 0, 0, 0};
    const float* bia[4] = {0, 0, 0, 0};
    int na = 0, nw = 0, nb = 0;
    for (int i = 0; i < n_in; i++) {
        const int s = in_sizes[i];
        if (s == NTOK * DM)      { if (na < 3) act[na++] = (const float*)d_in[i]; }
        else if (s == DM * DM)   { if (nw < 4) wgt[nw++] = (const float*)d_in[i]; }
        else if (s == DM)        { if (nb < 4) bia[nb++] = (const float*)d_in[i]; }
    }
    const float* query = act[0];
    const float* key   = act[1];
    const float* value = act[2];
    const float* Wq = wgt[0]; const float* Wk = wgt[1];
    const float* Wv = wgt[2]; const float* Wo = wgt[3];
    const float* bq = bia[0]; const float* bk = bia[1];
    const float* bv = bia[2]; const float* bo = bia[3];
    float* out = (float*)d_out;

    const dim3 ggrid(DM / 32, NTOK / 32);   // (32, 256)
    const dim3 gblk(32, 32);

    // QKV projections (write to device-global scratch via selector)
    gemm32<<<ggrid, gblk>>>(query, Wq, bq, out, 0, 0);   // -> g_q
    gemm32<<<ggrid, gblk>>>(key,   Wk, bk, out, 1, 0);   // -> g_k
    gemm32<<<ggrid, gblk>>>(value, Wv, bv, out, 2, 0);   // -> g_v

    // RoPE in place on g_q, g_k
    rope_naive<<<NTOK, 512>>>();

    // attention -> g_ctx
    attn_naive<<<dim3(SEQ, NH, BATCH), 256>>>();

    // output projection: g_ctx @ Wo^T + bo -> out
    gemm32<<<ggrid, gblk>>>(query, Wo, bo, out, 3, 1);
}

// round 4
// speedup vs baseline: 1.3537x; 1.3537x over previous
#include <cuda_runtime.h>
#include <math.h>

// Problem constants
#define BATCH 16
#define SEQ 512
#define DM 1024
#define NH 16
#define HD 64
#define NTOK (BATCH * SEQ)   // 8192

// ---------------- scratch (allocation-free: __device__ globals) ----------------
__device__ float g_q[NTOK * DM];
__device__ float g_k[NTOK * DM];
__device__ float g_v[NTOK * DM];
__device__ float g_ctx[NTOK * DM];

// ---------------- fast fp32 GEMM: C[m,n] = sum_k A[m,k]*W[n,k] + bias[n] ------
// 128x128 tile, BK=8, 256 threads, 8x8 accumulators per thread.
// dst_sel: 0->g_q, 1->g_k, 2->g_v, 3->Cout(param)
// src_sel: 0->Ain(param), 1->g_ctx
__global__ __launch_bounds__(256) void gemm_fast(
    const float* __restrict__ Ain, const float* __restrict__ W,
    const float* __restrict__ bias, float* Cout,
    int dst_sel, int src_sel)
{
    const float* A = (src_sel == 0) ? Ain : g_ctx;
    float* C = (dst_sel == 0) ? g_q
             : (dst_sel == 1) ? g_k
             : (dst_sel == 2) ? g_v
             : Cout;

    __shared__ __align__(16) float As[8][128];
    __shared__ __align__(16) float Bs[8][128];

    const int tid = threadIdx.x;
    const int bm = blockIdx.y * 128;
    const int bn = blockIdx.x * 128;

    const int lr = tid >> 1;          // 0..127
    const int lc = (tid & 1) * 4;     // 0 or 4

    const float* Ag = A + (size_t)(bm + lr) * DM + lc;
    const float* Wg = W + (size_t)(bn + lr) * DM + lc;

    const int trow = (tid >> 4) * 8;  // 0..120
    const int tcol = (tid & 15) * 8;  // 0..120

    float acc[8][8];
    #pragma unroll
    for (int i = 0; i < 8; i++)
        #pragma unroll
        for (int j = 0; j < 8; j++) acc[i][j] = 0.f;

    for (int k0 = 0; k0 < DM; k0 += 8) {
        const float4 av = *reinterpret_cast<const float4*>(Ag + k0);
        const float4 wv = *reinterpret_cast<const float4*>(Wg + k0);
        As[lc + 0][lr] = av.x; As[lc + 1][lr] = av.y;
        As[lc + 2][lr] = av.z; As[lc + 3][lr] = av.w;
        Bs[lc + 0][lr] = wv.x; Bs[lc + 1][lr] = wv.y;
        Bs[lc + 2][lr] = wv.z; Bs[lc + 3][lr] = wv.w;
        __syncthreads();

        #pragma unroll
        for (int kk = 0; kk < 8; kk++) {
            const float4 a0 = *reinterpret_cast<const float4*>(&As[kk][trow]);
            const float4 a1 = *reinterpret_cast<const float4*>(&As[kk][trow + 4]);
            const float4 b0 = *reinterpret_cast<const float4*>(&Bs[kk][tcol]);
            const float4 b1 = *reinterpret_cast<const float4*>(&Bs[kk][tcol + 4]);
            const float a[8] = {a0.x, a0.y, a0.z, a0.w, a1.x, a1.y, a1.z, a1.w};
            const float b[8] = {b0.x, b0.y, b0.z, b0.w, b1.x, b1.y, b1.z, b1.w};
            #pragma unroll
            for (int i = 0; i < 8; i++)
                #pragma unroll
                for (int j = 0; j < 8; j++)
                    acc[i][j] = fmaf(a[i], b[j], acc[i][j]);
        }
        __syncthreads();
    }

    #pragma unroll
    for (int i = 0; i < 8; i++) {
        float* cp = C + (size_t)(bm + trow + i) * DM + bn + tcol;
        const float* bp = bias + bn + tcol;
        float4 o0, o1;
        o0.x = acc[i][0] + bp[0]; o0.y = acc[i][1] + bp[1];
        o0.z = acc[i][2] + bp[2]; o0.w = acc[i][3] + bp[3];
        o1.x = acc[i][4] + bp[4]; o1.y = acc[i][5] + bp[5];
        o1.z = acc[i][6] + bp[6]; o1.w = acc[i][7] + bp[7];
        *reinterpret_cast<float4*>(cp)     = o0;
        *reinterpret_cast<float4*>(cp + 4) = o1;
    }
}

// ---------------- RoPE (verified in round 3, unchanged) -----------------------
__global__ __launch_bounds__(512) void rope_naive()
{
    const int token = blockIdx.x;            // 0..8191
    const int pos = token & (SEQ - 1);       // position within sequence
    const int h = threadIdx.x >> 5;          // 0..15
    const int i = threadIdx.x & 31;          // 0..31 pair index

    const float expo = (float)(2 * i) / 64.0f;
    const float invf = 1.0f / powf(10000.0f, expo);
    const float ang = (float)pos * invf;
    const float c = cosf(ang);
    const float s = sinf(ang);

    const size_t base = (size_t)token * DM + h * HD;
    float a = g_q[base + i], b = g_q[base + i + 32];
    g_q[base + i]      = a * c - b * s;
    g_q[base + i + 32] = b * c + a * s;
    a = g_k[base + i];  b = g_k[base + i + 32];
    g_k[base + i]      = a * c - b * s;
    g_k[base + i + 32] = b * c + a * s;
}

// ---------------- naive attention (verified in round 3, unchanged) ------------
__global__ __launch_bounds__(256) void attn_naive()
{
    __shared__ float qrow[HD];
    __shared__ float p[SEQ];
    __shared__ float red[256];

    const int qpos = blockIdx.x;   // 0..511
    const int h = blockIdx.y;      // 0..15
    const int b = blockIdx.z;      // 0..15
    const int tid = threadIdx.x;   // 0..255
    const size_t base = (size_t)b * SEQ * DM + (size_t)h * HD;

    // load q row (64 floats)
    if (tid < HD) qrow[tid] = g_q[base + (size_t)qpos * DM + tid];
    __syncthreads();

    // scores: thread handles k = tid and k = tid + 256
    for (int k = tid; k < SEQ; k += 256) {
        const float* kr = &g_k[base + (size_t)k * DM];
        float s = 0.f;
        for (int d = 0; d < HD; d++)
            s += qrow[d] * kr[d];
        p[k] = s * 0.125f;    // scale = 1/sqrt(64)
    }
    __syncthreads();

    // max reduction
    red[tid] = fmaxf(p[tid], p[tid + 256]);
    __syncthreads();
    for (int off = 128; off > 0; off >>= 1) {
        if (tid < off) red[tid] = fmaxf(red[tid], red[tid + off]);
        __syncthreads();
    }
    const float mx = red[0];
    __syncthreads();   // everyone has read red[0] before reuse

    // exp + sum reduction
    const float e0 = expf(p[tid] - mx);
    const float e1 = expf(p[tid + 256] - mx);
    p[tid] = e0;
    p[tid + 256] = e1;
    red[tid] = e0 + e1;
    __syncthreads();
    for (int off = 128; off > 0; off >>= 1) {
        if (tid < off) red[tid] += red[tid + off];
        __syncthreads();
    }
    const float inv = 1.0f / red[0];
    __syncthreads();   // everyone has read red[0] before reuse

    // out[d] = inv * sum_k p[k] * V[k][d]
    {
        const int d = tid & 63;
        const int kq = tid >> 6;
        float acc = 0.f;
        for (int k = kq * 128; k < kq * 128 + 128; k++)
            acc += p[k] * g_v[base + (size_t)k * DM + d];
        red[tid] = acc;
    }
    __syncthreads();
    if (tid < HD) {
        const float r = red[tid] + red[tid + 64] + red[tid + 128] + red[tid + 192];
        g_ctx[(size_t)(b * SEQ + qpos) * DM + h * HD + tid] = r * inv;
    }
}

// ---------------- launch -------------------------------------------------------
extern "C" void kernel_launch(void* const* d_in, const int* in_sizes, int n_in,
                              void* d_out, int out_size)
{
    // classify inputs by size (identity under dict order:
    // query,key,value, Wq,bq, Wk,bk, Wv,bv, Wo,bo)
    const float* act[3] = {0, 0, 0};
    const float* wgt[4] = {0, 0, 0, 0};
    const float* bia[4] = {0, 0, 0, 0};
    int na = 0, nw = 0, nb = 0;
    for (int i = 0; i < n_in; i++) {
        const int s = in_sizes[i];
        if (s == NTOK * DM)      { if (na < 3) act[na++] = (const float*)d_in[i]; }
        else if (s == DM * DM)   { if (nw < 4) wgt[nw++] = (const float*)d_in[i]; }
        else if (s == DM)        { if (nb < 4) bia[nb++] = (const float*)d_in[i]; }
    }
    const float* query = act[0];
    const float* key   = act[1];
    const float* value = act[2];
    const float* Wq = wgt[0]; const float* Wk = wgt[1];
    const float* Wv = wgt[2]; const float* Wo = wgt[3];
    const float* bq = bia[0]; const float* bk = bia[1];
    const float* bv = bia[2]; const float* bo = bia[3];
    float* out = (float*)d_out;

    const dim3 ggrid(DM / 128, NTOK / 128);   // (8, 64)
    const dim3 gblk(256);

    // QKV projections -> g_q, g_k, g_v
    gemm_fast<<<ggrid, gblk>>>(query, Wq, bq, out, 0, 0);
    gemm_fast<<<ggrid, gblk>>>(key,   Wk, bk, out, 1, 0);
    gemm_fast<<<ggrid, gblk>>>(value, Wv, bv, out, 2, 0);

    // RoPE in place on g_q, g_k
    rope_naive<<<NTOK, 512>>>();

    // attention -> g_ctx
    attn_naive<<<dim3(SEQ, NH, BATCH), 256>>>();

    // output projection: g_ctx @ Wo^T + bo -> out
    gemm_fast<<<ggrid, gblk>>>(query, Wo, bo, out, 3, 1);
}

// round 5
// speedup vs baseline: 9.0009x; 6.6490x over previous
#include <cuda_runtime.h>
#include <math.h>

// Problem constants
#define BATCH 16
#define SEQ 512
#define DM 1024
#define NH 16
#define HD 64
#define NTOK (BATCH * SEQ)   // 8192

// ---------------- scratch (allocation-free: __device__ globals) ----------------
__device__ float g_q[NTOK * DM];
__device__ float g_k[NTOK * DM];
__device__ float g_v[NTOK * DM];
__device__ float g_ctx[NTOK * DM];

// ---------------- fast fp32 GEMM: C[m,n] = sum_k A[m,k]*W[n,k] + bias[n] ------
// 128x128 tile, BK=8, 256 threads, 8x8 accumulators per thread.
// dst_sel: 0->g_q, 1->g_k, 2->g_v, 3->Cout(param)
// src_sel: 0->Ain(param), 1->g_ctx
__global__ __launch_bounds__(256) void gemm_fast(
    const float* __restrict__ Ain, const float* __restrict__ W,
    const float* __restrict__ bias, float* Cout,
    int dst_sel, int src_sel)
{
    const float* A = (src_sel == 0) ? Ain : g_ctx;
    float* C = (dst_sel == 0) ? g_q
             : (dst_sel == 1) ? g_k
             : (dst_sel == 2) ? g_v
             : Cout;

    __shared__ __align__(16) float As[8][128];
    __shared__ __align__(16) float Bs[8][128];

    const int tid = threadIdx.x;
    const int bm = blockIdx.y * 128;
    const int bn = blockIdx.x * 128;

    const int lr = tid >> 1;          // 0..127
    const int lc = (tid & 1) * 4;     // 0 or 4

    const float* Ag = A + (size_t)(bm + lr) * DM + lc;
    const float* Wg = W + (size_t)(bn + lr) * DM + lc;

    const int trow = (tid >> 4) * 8;  // 0..120
    const int tcol = (tid & 15) * 8;  // 0..120

    float acc[8][8];
    #pragma unroll
    for (int i = 0; i < 8; i++)
        #pragma unroll
        for (int j = 0; j < 8; j++) acc[i][j] = 0.f;

    for (int k0 = 0; k0 < DM; k0 += 8) {
        const float4 av = *reinterpret_cast<const float4*>(Ag + k0);
        const float4 wv = *reinterpret_cast<const float4*>(Wg + k0);
        As[lc + 0][lr] = av.x; As[lc + 1][lr] = av.y;
        As[lc + 2][lr] = av.z; As[lc + 3][lr] = av.w;
        Bs[lc + 0][lr] = wv.x; Bs[lc + 1][lr] = wv.y;
        Bs[lc + 2][lr] = wv.z; Bs[lc + 3][lr] = wv.w;
        __syncthreads();

        #pragma unroll
        for (int kk = 0; kk < 8; kk++) {
            const float4 a0 = *reinterpret_cast<const float4*>(&As[kk][trow]);
            const float4 a1 = *reinterpret_cast<const float4*>(&As[kk][trow + 4]);
            const float4 b0 = *reinterpret_cast<const float4*>(&Bs[kk][tcol]);
            const float4 b1 = *reinterpret_cast<const float4*>(&Bs[kk][tcol + 4]);
            const float a[8] = {a0.x, a0.y, a0.z, a0.w, a1.x, a1.y, a1.z, a1.w};
            const float b[8] = {b0.x, b0.y, b0.z, b0.w, b1.x, b1.y, b1.z, b1.w};
            #pragma unroll
            for (int i = 0; i < 8; i++)
                #pragma unroll
                for (int j = 0; j < 8; j++)
                    acc[i][j] = fmaf(a[i], b[j], acc[i][j]);
        }
        __syncthreads();
    }

    #pragma unroll
    for (int i = 0; i < 8; i++) {
        float* cp = C + (size_t)(bm + trow + i) * DM + bn + tcol;
        const float* bp = bias + bn + tcol;
        float4 o0, o1;
        o0.x = acc[i][0] + bp[0]; o0.y = acc[i][1] + bp[1];
        o0.z = acc[i][2] + bp[2]; o0.w = acc[i][3] + bp[3];
        o1.x = acc[i][4] + bp[4]; o1.y = acc[i][5] + bp[5];
        o1.z = acc[i][6] + bp[6]; o1.w = acc[i][7] + bp[7];
        *reinterpret_cast<float4*>(cp)     = o0;
        *reinterpret_cast<float4*>(cp + 4) = o1;
    }
}

// ---------------- RoPE (verified; unchanged from round 3/4) -------------------
__global__ __launch_bounds__(512) void rope_naive()
{
    const int token = blockIdx.x;            // 0..8191
    const int pos = token & (SEQ - 1);       // position within sequence
    const int h = threadIdx.x >> 5;          // 0..15
    const int i = threadIdx.x & 31;          // 0..31 pair index

    const float expo = (float)(2 * i) / 64.0f;
    const float invf = 1.0f / powf(10000.0f, expo);
    const float ang = (float)pos * invf;
    const float c = cosf(ang);
    const float s = sinf(ang);

    const size_t base = (size_t)token * DM + h * HD;
    float a = g_q[base + i], b = g_q[base + i + 32];
    g_q[base + i]      = a * c - b * s;
    g_q[base + i + 32] = b * c + a * s;
    a = g_k[base + i];  b = g_k[base + i + 32];
    g_k[base + i]      = a * c - b * s;
    g_k[base + i + 32] = b * c + a * s;
}

// ---------------- fast flash attention (no pointer args: direct globals) ------
// CTA per (b, h, 64-query tile). 256 threads.
// Thread (qb = tid>>4, kb = tid&15) owns a 4q x 4k score block and 4q x 4d output.
// Online softmax; row reductions via 16-lane XOR shuffles (offsets 1,2,4,8 stay
// within each 16-lane half-warp, which is exactly one qb group).
#define SP 65   // padded stride for Qs/Ks/Ps/Vs

__global__ __launch_bounds__(256) void attn_fast()
{
    extern __shared__ float sm[];
    float* Qs = sm;                 // 64 * SP
    float* Ks = sm + 64 * SP;
    float* Vs = sm + 2 * 64 * SP;
    float* Ps = sm + 3 * 64 * SP;   // separate buffer, no aliasing

    const int tid = threadIdx.x;
    const int q0 = blockIdx.x * 64;
    const int h  = blockIdx.y;
    const int b  = blockIdx.z;
    const size_t base = (size_t)b * SEQ * DM + (size_t)h * HD;  // + pos*DM + d

    // cooperative tile loader mapping: row r, 16-float chunk at d0
    const int r  = tid >> 2;          // 0..63
    const int d0 = (tid & 3) * 16;    // 0,16,32,48

    // ---- load Q tile (64 x 64), pre-scaled by 1/sqrt(HD) = 0.125 ----
    {
        const float* src = &g_q[base + (size_t)(q0 + r) * DM + d0];
        #pragma unroll
        for (int t = 0; t < 4; t++) {
            const float4 v = reinterpret_cast<const float4*>(src)[t];
            Qs[r * SP + d0 + 4 * t + 0] = 0.125f * v.x;
            Qs[r * SP + d0 + 4 * t + 1] = 0.125f * v.y;
            Qs[r * SP + d0 + 4 * t + 2] = 0.125f * v.z;
            Qs[r * SP + d0 + 4 * t + 3] = 0.125f * v.w;
        }
    }

    const int qb = tid >> 4;   // 0..15 (q group)
    const int kb = tid & 15;   // 0..15 (k group)

    float o[4][4];
    float m[4], l[4];
    #pragma unroll
    for (int i = 0; i < 4; i++) {
        m[i] = -3.0e38f; l[i] = 0.f;
        #pragma unroll
        for (int j = 0; j < 4; j++) o[i][j] = 0.f;
    }

    for (int kt = 0; kt < SEQ; kt += 64) {
        // ---- load K and V tiles (64 x 64 each) ----
        {
            const float* ksrc = &g_k[base + (size_t)(kt + r) * DM + d0];
            const float* vsrc = &g_v[base + (size_t)(kt + r) * DM + d0];
            #pragma unroll
            for (int t = 0; t < 4; t++) {
                const float4 kv = reinterpret_cast<const float4*>(ksrc)[t];
                Ks[r * SP + d0 + 4 * t + 0] = kv.x;
                Ks[r * SP + d0 + 4 * t + 1] = kv.y;
                Ks[r * SP + d0 + 4 * t + 2] = kv.z;
                Ks[r * SP + d0 + 4 * t + 3] = kv.w;
                const float4 vv = reinterpret_cast<const float4*>(vsrc)[t];
                Vs[r * SP + d0 + 4 * t + 0] = vv.x;
                Vs[r * SP + d0 + 4 * t + 1] = vv.y;
                Vs[r * SP + d0 + 4 * t + 2] = vv.z;
                Vs[r * SP + d0 + 4 * t + 3] = vv.w;
            }
        }
        __syncthreads();   // tiles visible (first iter: also covers Q)

        // ---- scores: sc[i][j] = (Q/8)[q0+qb*4+i] . K[kt+kb*4+j] ----
        float sc[4][4];
        #pragma unroll
        for (int i = 0; i < 4; i++)
            #pragma unroll
            for (int j = 0; j < 4; j++) sc[i][j] = 0.f;

        #pragma unroll 4
        for (int d = 0; d < HD; d++) {
            float qv[4], kv[4];
            #pragma unroll
            for (int i = 0; i < 4; i++) qv[i] = Qs[(qb * 4 + i) * SP + d];
            #pragma unroll
            for (int j = 0; j < 4; j++) kv[j] = Ks[(kb * 4 + j) * SP + d];
            #pragma unroll
            for (int i = 0; i < 4; i++)
                #pragma unroll
                for (int j = 0; j < 4; j++)
                    sc[i][j] = fmaf(qv[i], kv[j], sc[i][j]);
        }

        // ---- online softmax update ----
        #pragma unroll
        for (int i = 0; i < 4; i++) {
            float tm = fmaxf(fmaxf(sc[i][0], sc[i][1]), fmaxf(sc[i][2], sc[i][3]));
            #pragma unroll
            for (int off = 1; off < 16; off <<= 1)
                tm = fmaxf(tm, __shfl_xor_sync(0xffffffffu, tm, off));
            const float nm = fmaxf(m[i], tm);
            const float corr = __expf(m[i] - nm);
            float srow = 0.f;
            #pragma unroll
            for (int j = 0; j < 4; j++) {
                sc[i][j] = __expf(sc[i][j] - nm);
                srow += sc[i][j];
            }
            #pragma unroll
            for (int off = 1; off < 16; off <<= 1)
                srow += __shfl_xor_sync(0xffffffffu, srow, off);
            l[i] = l[i] * corr + srow;
            m[i] = nm;
            #pragma unroll
            for (int j = 0; j < 4; j++) o[i][j] *= corr;
        }

        // ---- publish P (each thread writes only its own 4x4 block) ----
        #pragma unroll
        for (int i = 0; i < 4; i++)
            #pragma unroll
            for (int j = 0; j < 4; j++)
                Ps[(qb * 4 + i) * SP + kb * 4 + j] = sc[i][j];
        __syncthreads();   // P visible

        // ---- PV: o[i][j] += sum_k P[q][k] * V[k][kb*4+j] ----
        #pragma unroll 4
        for (int k = 0; k < 64; k++) {
            float pv[4], vv[4];
            #pragma unroll
            for (int i = 0; i < 4; i++) pv[i] = Ps[(qb * 4 + i) * SP + k];
            #pragma unroll
            for (int j = 0; j < 4; j++) vv[j] = Vs[k * SP + kb * 4 + j];
            #pragma unroll
            for (int i = 0; i < 4; i++)
                #pragma unroll
                for (int j = 0; j < 4; j++)
                    o[i][j] = fmaf(pv[i], vv[j], o[i][j]);
        }
        __syncthreads();   // PV reads done before next tile overwrites Ks/Vs/Ps
    }

    // ---- epilogue: normalize, store ctx in [B,S,D] layout ----
    #pragma unroll
    for (int i = 0; i < 4; i++) {
        const float inv = 1.0f / l[i];
        float* dst = &g_ctx[(size_t)(b * SEQ + q0 + qb * 4 + i) * DM + h * HD + kb * 4];
        #pragma unroll
        for (int j = 0; j < 4; j++) dst[j] = o[i][j] * inv;
    }
}

// ---------------- launch -------------------------------------------------------
extern "C" void kernel_launch(void* const* d_in, const int* in_sizes, int n_in,
                              void* d_out, int out_size)
{
    // classify inputs by size (identity under dict order:
    // query,key,value, Wq,bq, Wk,bk, Wv,bv, Wo,bo)
    const float* act[3] = {0, 0, 0};
    const float* wgt[4] = {0, 0, 0, 0};
    const float* bia[4] = {0, 0, 0, 0};
    int na = 0, nw = 0, nb = 0;
    for (int i = 0; i < n_in; i++) {
        const int s = in_sizes[i];
        if (s == NTOK * DM)      { if (na < 3) act[na++] = (const float*)d_in[i]; }
        else if (s == DM * DM)   { if (nw < 4) wgt[nw++] = (const float*)d_in[i]; }
        else if (s == DM)        { if (nb < 4) bia[nb++] = (const float*)d_in[i]; }
    }
    const float* query = act[0];
    const float* key   = act[1];
    const float* value = act[2];
    const float* Wq = wgt[0]; const float* Wk = wgt[1];
    const float* Wv = wgt[2]; const float* Wo = wgt[3];
    const float* bq = bia[0]; const float* bk = bia[1];
    const float* bv = bia[2]; const float* bo = bia[3];
    float* out = (float*)d_out;

    const dim3 ggrid(DM / 128, NTOK / 128);   // (8, 64)
    const dim3 gblk(256);

    // QKV projections -> g_q, g_k, g_v
    gemm_fast<<<ggrid, gblk>>>(query, Wq, bq, out, 0, 0);
    gemm_fast<<<ggrid, gblk>>>(key,   Wk, bk, out, 1, 0);
    gemm_fast<<<ggrid, gblk>>>(value, Wv, bv, out, 2, 0);

    // RoPE in place on g_q, g_k
    rope_naive<<<NTOK, 512>>>();

    // fast flash attention -> g_ctx
    const int smem = 4 * 64 * SP * (int)sizeof(float);   // 66560 B
    cudaFuncSetAttribute(attn_fast, cudaFuncAttributeMaxDynamicSharedMemorySize, smem);
    attn_fast<<<dim3(SEQ / 64, NH, BATCH), 256, smem>>>();

    // output projection: g_ctx @ Wo^T + bo -> out
    gemm_fast<<<ggrid, gblk>>>(query, Wo, bo, out, 3, 1);
}

// round 7
// speedup vs baseline: 16.1783x; 1.7974x over previous
#include <cuda_runtime.h>
#include <cuda_bf16.h>
#include <stdint.h>
#include <math.h>

// Problem constants
#define BATCH 16
#define SEQ 512
#define DM 1024
#define NH 16
#define HD 64
#define NTOK (BATCH * SEQ)   // 8192

// ---------------- scratch (allocation-free: __device__ globals) ----------------
__device__ float g_q[NTOK * DM];
__device__ float g_k[NTOK * DM];
__device__ float g_v[NTOK * DM];
__device__ float g_ctx[NTOK * DM];

// ---------------- warp-level tensor core primitives (sm_80+, no 'a' target) ----
__device__ __forceinline__ uint32_t smem_u32(const void* p) {
    uint32_t a;
    asm("{ .reg .u64 t; cvta.to.shared.u64 t, %1; cvt.u32.u64 %0, t; }"
        : "=r"(a) : "l"(p));
    return a;
}
__device__ __forceinline__ void ldm_x4(uint32_t* r, uint32_t addr) {
    asm volatile("ldmatrix.sync.aligned.m8n8.x4.shared.b16 {%0,%1,%2,%3}, [%4];"
        : "=r"(r[0]), "=r"(r[1]), "=r"(r[2]), "=r"(r[3]) : "r"(addr));
}
__device__ __forceinline__ void ldm_x2(uint32_t* r, uint32_t addr) {
    asm volatile("ldmatrix.sync.aligned.m8n8.x2.shared.b16 {%0,%1}, [%2];"
        : "=r"(r[0]), "=r"(r[1]) : "r"(addr));
}
__device__ __forceinline__ void mma_bf16(float* d, const uint32_t* a, const uint32_t* b) {
    asm volatile("mma.sync.aligned.m16n8k16.row.col.f32.bf16.bf16.f32 "
        "{%0,%1,%2,%3}, {%4,%5,%6,%7}, {%8,%9}, {%0,%1,%2,%3};"
        : "+f"(d[0]), "+f"(d[1]), "+f"(d[2]), "+f"(d[3])
        : "r"(a[0]), "r"(a[1]), "r"(a[2]), "r"(a[3]), "r"(b[0]), "r"(b[1]));
}

// ================== mma.sync bf16-split GEMM ===================================
// C[m,n] = sum_k A[m,k] * W[n,k] + bias[n];  M=NTOK, N=K=DM.
// fp32 split: hi = trunc_bf16(x), lo = trunc_bf16(x - hi).
// D += Ah*Bh + Ah*Bl + Al*Bh   (fp32 accumulate; lo*lo dropped, ~2^-16 rel)
// CTA: 128x128 tile, 256 threads = 8 warps (2 m x 4 n), warp tile 64x32, BK=32.
#define GST 40   // smem row stride in bf16 (80 B: 16B-aligned, ldmatrix conflict-free)

__device__ __forceinline__ void split_pack16(const float* f, uint4* hi, uint4* lo) {
    uint32_t uh[16], ul[16];
    #pragma unroll
    for (int j = 0; j < 16; j++) {
        const uint32_t u = __float_as_uint(f[j]);
        uh[j] = u;
        ul[j] = __float_as_uint(f[j] - __uint_as_float(u & 0xFFFF0000u));
    }
    #pragma unroll
    for (int g = 0; g < 2; g++) {
        hi[g].x = __byte_perm(uh[8*g+0], uh[8*g+1], 0x7632);
        hi[g].y = __byte_perm(uh[8*g+2], uh[8*g+3], 0x7632);
        hi[g].z = __byte_perm(uh[8*g+4], uh[8*g+5], 0x7632);
        hi[g].w = __byte_perm(uh[8*g+6], uh[8*g+7], 0x7632);
        lo[g].x = __byte_perm(ul[8*g+0], ul[8*g+1], 0x7632);
        lo[g].y = __byte_perm(ul[8*g+2], ul[8*g+3], 0x7632);
        lo[g].z = __byte_perm(ul[8*g+4], ul[8*g+5], 0x7632);
        lo[g].w = __byte_perm(ul[8*g+6], ul[8*g+7], 0x7632);
    }
}

// dst_sel: 0->g_q, 1->g_k, 2->g_v, 3->Cout;  src_sel: 0->Ain, 1->g_ctx
__global__ __launch_bounds__(256) void gemm_mma(
    const float* __restrict__ Ain, const float* __restrict__ W,
    const float* __restrict__ bias, float* Cout,
    int dst_sel, int src_sel)
{
    const float* A = (src_sel == 0) ? Ain : g_ctx;
    float* C = (dst_sel == 0) ? g_q
             : (dst_sel == 1) ? g_k
             : (dst_sel == 2) ? g_v
             : Cout;

    __shared__ __align__(16) __nv_bfloat16 sAh[128 * GST];
    __shared__ __align__(16) __nv_bfloat16 sAl[128 * GST];
    __shared__ __align__(16) __nv_bfloat16 sBh[128 * GST];
    __shared__ __align__(16) __nv_bfloat16 sBl[128 * GST];

    const int tid = threadIdx.x;
    const int lane = tid & 31;
    const int wid = tid >> 5;
    const int wm = wid & 1;    // warp m: 0..1 (64 rows each)
    const int wn = wid >> 1;   // warp n: 0..3 (32 cols each)
    const int bm = blockIdx.y * 128;
    const int bn = blockIdx.x * 128;

    // gmem loader mapping: 16 consecutive floats per thread
    const int grow = tid >> 1;           // 0..127
    const int gcol = (tid & 1) * 16;     // 0 or 16

    const uint32_t aHiB = smem_u32(sAh), aLoB = smem_u32(sAl);
    const uint32_t bHiB = smem_u32(sBh), bLoB = smem_u32(sBl);

    // ldmatrix fragment addresses (constant across iterations)
    const int la = lane & 15;
    // A: row = wm*64 + mt*16 + (lane&15), col-half = (lane>>4)*8, within kk*16
    const uint32_t aRowOff = (uint32_t)((wm * 64 + la) * GST + (lane >> 4) * 8) * 2;
    // B: row(n) = wn*32 + nt*8 + (la&7), col-half = (la>>3)*8
    const uint32_t bRowOff = (uint32_t)((wn * 32 + (la & 7)) * GST + ((la >> 3) & 1) * 8) * 2;

    float acc[4][4][4];
    #pragma unroll
    for (int mt = 0; mt < 4; mt++)
        #pragma unroll
        for (int nt = 0; nt < 4; nt++)
            #pragma unroll
            for (int e = 0; e < 4; e++) acc[mt][nt][e] = 0.f;

    // prefetch chunk 0
    float aR[16], bR[16];
    {
        const float* ap = A + (size_t)(bm + grow) * DM + gcol;
        const float* bp = W + (size_t)(bn + grow) * DM + gcol;
        #pragma unroll
        for (int t = 0; t < 4; t++) {
            *reinterpret_cast<float4*>(&aR[4 * t]) = reinterpret_cast<const float4*>(ap)[t];
            *reinterpret_cast<float4*>(&bR[4 * t]) = reinterpret_cast<const float4*>(bp)[t];
        }
    }

    #pragma unroll 1
    for (int it = 0; it < DM / 32; it++) {
        // split + store prefetched chunk
        {
            uint4 hi[2], lo[2];
            split_pack16(aR, hi, lo);
            const int off = grow * GST + gcol;
            *reinterpret_cast<uint4*>(&sAh[off]) = hi[0];
            *reinterpret_cast<uint4*>(&sAh[off + 8]) = hi[1];
            *reinterpret_cast<uint4*>(&sAl[off]) = lo[0];
            *reinterpret_cast<uint4*>(&sAl[off + 8]) = lo[1];
            split_pack16(bR, hi, lo);
            *reinterpret_cast<uint4*>(&sBh[off]) = hi[0];
            *reinterpret_cast<uint4*>(&sBh[off + 8]) = hi[1];
            *reinterpret_cast<uint4*>(&sBl[off]) = lo[0];
            *reinterpret_cast<uint4*>(&sBl[off + 8]) = lo[1];
        }
        __syncthreads();

        // prefetch next chunk (overlaps with MMA burst below)
        if (it + 1 < DM / 32) {
            const float* ap = A + (size_t)(bm + grow) * DM + (it + 1) * 32 + gcol;
            const float* bp = W + (size_t)(bn + grow) * DM + (it + 1) * 32 + gcol;
            #pragma unroll
            for (int t = 0; t < 4; t++) {
                *reinterpret_cast<float4*>(&aR[4 * t]) = reinterpret_cast<const float4*>(ap)[t];
                *reinterpret_cast<float4*>(&bR[4 * t]) = reinterpret_cast<const float4*>(bp)[t];
            }
        }

        #pragma unroll
        for (int kk = 0; kk < 2; kk++) {
            const uint32_t kOff = (uint32_t)(kk * 16) * 2;
            uint32_t ah[4][4], al[4][4];
            #pragma unroll
            for (int mt = 0; mt < 4; mt++) {
                const uint32_t ro = aRowOff + (uint32_t)(mt * 16 * GST) * 2 + kOff;
                ldm_x4(ah[mt], aHiB + ro);
                ldm_x4(al[mt], aLoB + ro);
            }
            #pragma unroll
            for (int nt = 0; nt < 4; nt++) {
                const uint32_t ro = bRowOff + (uint32_t)(nt * 8 * GST) * 2 + kOff;
                uint32_t bh[2], bl[2];
                ldm_x2(bh, bHiB + ro);
                ldm_x2(bl, bLoB + ro);
                #pragma unroll
                for (int mt = 0; mt < 4; mt++) {
                    mma_bf16(acc[mt][nt], ah[mt], bh);
                    mma_bf16(acc[mt][nt], ah[mt], bl);
                    mma_bf16(acc[mt][nt], al[mt], bh);
                }
            }
        }
        __syncthreads();
    }

    // epilogue: D frag (t/4 = row-in-8, (t%4)*2 = col), + bias, float2 stores
    const int er = lane >> 2;          // 0..7
    const int ec = (lane & 3) * 2;     // 0,2,4,6
    #pragma unroll
    for (int mt = 0; mt < 4; mt++) {
        #pragma unroll
        for (int nt = 0; nt < 4; nt++) {
            const int col = bn + wn * 32 + nt * 8 + ec;
            const float b0 = bias[col], b1 = bias[col + 1];
            const int r0 = bm + wm * 64 + mt * 16 + er;
            float2 v0, v1;
            v0.x = acc[mt][nt][0] + b0; v0.y = acc[mt][nt][1] + b1;
            v1.x = acc[mt][nt][2] + b0; v1.y = acc[mt][nt][3] + b1;
            *reinterpret_cast<float2*>(&C[(size_t)r0 * DM + col]) = v0;
            *reinterpret_cast<float2*>(&C[(size_t)(r0 + 8) * DM + col]) = v1;
        }
    }
}

// ---------------- RoPE (verified; unchanged) -----------------------------------
__global__ __launch_bounds__(512) void rope_naive()
{
    const int token = blockIdx.x;
    const int pos = token & (SEQ - 1);
    const int h = threadIdx.x >> 5;
    const int i = threadIdx.x & 31;

    const float expo = (float)(2 * i) / 64.0f;
    const float invf = 1.0f / powf(10000.0f, expo);
    const float ang = (float)pos * invf;
    const float c = cosf(ang);
    const float s = sinf(ang);

    const size_t base = (size_t)token * DM + h * HD;
    float a = g_q[base + i], b = g_q[base + i + 32];
    g_q[base + i]      = a * c - b * s;
    g_q[base + i + 32] = b * c + a * s;
    a = g_k[base + i];  b = g_k[base + i + 32];
    g_k[base + i]      = a * c - b * s;
    g_k[base + i + 32] = b * c + a * s;
}

// ---------------- fast flash attention (verified; unchanged) -------------------
#define SP 65

__global__ __launch_bounds__(256) void attn_fast()
{
    extern __shared__ float sm[];
    float* Qs = sm;
    float* Ks = sm + 64 * SP;
    float* Vs = sm + 2 * 64 * SP;
    float* Ps = sm + 3 * 64 * SP;

    const int tid = threadIdx.x;
    const int q0 = blockIdx.x * 64;
    const int h  = blockIdx.y;
    const int b  = blockIdx.z;
    const size_t base = (size_t)b * SEQ * DM + (size_t)h * HD;

    const int r  = tid >> 2;
    const int d0 = (tid & 3) * 16;

    {
        const float* src = &g_q[base + (size_t)(q0 + r) * DM + d0];
        #pragma unroll
        for (int t = 0; t < 4; t++) {
            const float4 v = reinterpret_cast<const float4*>(src)[t];
            Qs[r * SP + d0 + 4 * t + 0] = 0.125f * v.x;
            Qs[r * SP + d0 + 4 * t + 1] = 0.125f * v.y;
            Qs[r * SP + d0 + 4 * t + 2] = 0.125f * v.z;
            Qs[r * SP + d0 + 4 * t + 3] = 0.125f * v.w;
        }
    }

    const int qb = tid >> 4;
    const int kb = tid & 15;

    float o[4][4];
    float m[4], l[4];
    #pragma unroll
    for (int i = 0; i < 4; i++) {
        m[i] = -3.0e38f; l[i] = 0.f;
        #pragma unroll
        for (int j = 0; j < 4; j++) o[i][j] = 0.f;
    }

    for (int kt = 0; kt < SEQ; kt += 64) {
        {
            const float* ksrc = &g_k[base + (size_t)(kt + r) * DM + d0];
            const float* vsrc = &g_v[base + (size_t)(kt + r) * DM + d0];
            #pragma unroll
            for (int t = 0; t < 4; t++) {
                const float4 kv = reinterpret_cast<const float4*>(ksrc)[t];
                Ks[r * SP + d0 + 4 * t + 0] = kv.x;
                Ks[r * SP + d0 + 4 * t + 1] = kv.y;
                Ks[r * SP + d0 + 4 * t + 2] = kv.z;
                Ks[r * SP + d0 + 4 * t + 3] = kv.w;
                const float4 vv = reinterpret_cast<const float4*>(vsrc)[t];
                Vs[r * SP + d0 + 4 * t + 0] = vv.x;
                Vs[r * SP + d0 + 4 * t + 1] = vv.y;
                Vs[r * SP + d0 + 4 * t + 2] = vv.z;
                Vs[r * SP + d0 + 4 * t + 3] = vv.w;
            }
        }
        __syncthreads();

        float sc[4][4];
        #pragma unroll
        for (int i = 0; i < 4; i++)
            #pragma unroll
            for (int j = 0; j < 4; j++) sc[i][j] = 0.f;

        #pragma unroll 4
        for (int d = 0; d < HD; d++) {
            float qv[4], kv[4];
            #pragma unroll
            for (int i = 0; i < 4; i++) qv[i] = Qs[(qb * 4 + i) * SP + d];
            #pragma unroll
            for (int j = 0; j < 4; j++) kv[j] = Ks[(kb * 4 + j) * SP + d];
            #pragma unroll
            for (int i = 0; i < 4; i++)
                #pragma unroll
                for (int j = 0; j < 4; j++)
                    sc[i][j] = fmaf(qv[i], kv[j], sc[i][j]);
        }

        #pragma unroll
        for (int i = 0; i < 4; i++) {
            float tm = fmaxf(fmaxf(sc[i][0], sc[i][1]), fmaxf(sc[i][2], sc[i][3]));
            #pragma unroll
            for (int off = 1; off < 16; off <<= 1)
                tm = fmaxf(tm, __shfl_xor_sync(0xffffffffu, tm, off));
            const float nm = fmaxf(m[i], tm);
            const float corr = __expf(m[i] - nm);
            float srow = 0.f;
            #pragma unroll
            for (int j = 0; j < 4; j++) {
                sc[i][j] = __expf(sc[i][j] - nm);
                srow += sc[i][j];
            }
            #pragma unroll
            for (int off = 1; off < 16; off <<= 1)
                srow += __shfl_xor_sync(0xffffffffu, srow, off);
            l[i] = l[i] * corr + srow;
            m[i] = nm;
            #pragma unroll
            for (int j = 0; j < 4; j++) o[i][j] *= corr;
        }

        #pragma unroll
        for (int i = 0; i < 4; i++)
            #pragma unroll
            for (int j = 0; j < 4; j++)
                Ps[(qb * 4 + i) * SP + kb * 4 + j] = sc[i][j];
        __syncthreads();

        #pragma unroll 4
        for (int k = 0; k < 64; k++) {
            float pv[4], vv[4];
            #pragma unroll
            for (int i = 0; i < 4; i++) pv[i] = Ps[(qb * 4 + i) * SP + k];
            #pragma unroll
            for (int j = 0; j < 4; j++) vv[j] = Vs[k * SP + kb * 4 + j];
            #pragma unroll
            for (int i = 0; i < 4; i++)
                #pragma unroll
                for (int j = 0; j < 4; j++)
                    o[i][j] = fmaf(pv[i], vv[j], o[i][j]);
        }
        __syncthreads();
    }

    #pragma unroll
    for (int i = 0; i < 4; i++) {
        const float inv = 1.0f / l[i];
        float* dst = &g_ctx[(size_t)(b * SEQ + q0 + qb * 4 + i) * DM + h * HD + kb * 4];
        #pragma unroll
        for (int j = 0; j < 4; j++) dst[j] = o[i][j] * inv;
    }
}

// ---------------- launch -------------------------------------------------------
extern "C" void kernel_launch(void* const* d_in, const int* in_sizes, int n_in,
                              void* d_out, int out_size)
{
    const float* act[3] = {0, 0, 0};
    const float* wgt[4] = {0, 0, 0, 0};
    const float* bia[4] = {0, 0, 0, 0};
    int na = 0, nw = 0, nb = 0;
    for (int i = 0; i < n_in; i++) {
        const int s = in_sizes[i];
        if (s == NTOK * DM)      { if (na < 3) act[na++] = (const float*)d_in[i]; }
        else if (s == DM * DM)   { if (nw < 4) wgt[nw++] = (const float*)d_in[i]; }
        else if (s == DM)        { if (nb < 4) bia[nb++] = (const float*)d_in[i]; }
    }
    const float* query = act[0];
    const float* key   = act[1];
    const float* value = act[2];
    const float* Wq = wgt[0]; const float* Wk = wgt[1];
    const float* Wv = wgt[2]; const float* Wo = wgt[3];
    const float* bq = bia[0]; const float* bk = bia[1];
    const float* bv = bia[2]; const float* bo = bia[3];
    float* out = (float*)d_out;

    const dim3 ggrid(DM / 128, NTOK / 128);   // (8, 64)

    // QKV projections -> g_q, g_k, g_v  (mma.sync bf16-split)
    gemm_mma<<<ggrid, 256>>>(query, Wq, bq, out, 0, 0);
    gemm_mma<<<ggrid, 256>>>(key,   Wk, bk, out, 1, 0);
    gemm_mma<<<ggrid, 256>>>(value, Wv, bv, out, 2, 0);

    // RoPE in place on g_q, g_k
    rope_naive<<<NTOK, 512>>>();

    // fast flash attention -> g_ctx
    const int smem = 4 * 64 * SP * (int)sizeof(float);   // 66560 B
    cudaFuncSetAttribute(attn_fast, cudaFuncAttributeMaxDynamicSharedMemorySize, smem);
    attn_fast<<<dim3(SEQ / 64, NH, BATCH), 256, smem>>>();

    // output projection: g_ctx @ Wo^T + bo -> out
    gemm_mma<<<ggrid, 256>>>(query, Wo, bo, out, 3, 1);
}

// round 8
// speedup vs baseline: 21.9845x; 1.3589x over previous
#include <cuda_runtime.h>
#include <cuda_bf16.h>
#include <stdint.h>
#include <math.h>

// Problem constants
#define BATCH 16
#define SEQ 512
#define DM 1024
#define NH 16
#define HD 64
#define NTOK (BATCH * SEQ)   // 8192

// ---------------- scratch (allocation-free: __device__ globals) ----------------
__device__ float g_q[NTOK * DM];
__device__ float g_k[NTOK * DM];
__device__ float g_v[NTOK * DM];
__device__ float g_ctx[NTOK * DM];

// ---------------- warp-level tensor core primitives (sm_80+, no 'a' target) ----
__device__ __forceinline__ uint32_t smem_u32(const void* p) {
    uint32_t a;
    asm("{ .reg .u64 t; cvta.to.shared.u64 t, %1; cvt.u32.u64 %0, t; }"
        : "=r"(a) : "l"(p));
    return a;
}
__device__ __forceinline__ void ldm_x4(uint32_t* r, uint32_t addr) {
    asm volatile("ldmatrix.sync.aligned.m8n8.x4.shared.b16 {%0,%1,%2,%3}, [%4];"
        : "=r"(r[0]), "=r"(r[1]), "=r"(r[2]), "=r"(r[3]) : "r"(addr));
}
__device__ __forceinline__ void ldm_x2(uint32_t* r, uint32_t addr) {
    asm volatile("ldmatrix.sync.aligned.m8n8.x2.shared.b16 {%0,%1}, [%2];"
        : "=r"(r[0]), "=r"(r[1]) : "r"(addr));
}
__device__ __forceinline__ void ldm_x2t(uint32_t* r, uint32_t addr) {
    asm volatile("ldmatrix.sync.aligned.m8n8.x2.trans.shared.b16 {%0,%1}, [%2];"
        : "=r"(r[0]), "=r"(r[1]) : "r"(addr));
}
__device__ __forceinline__ void mma_bf16(float* d, const uint32_t* a, const uint32_t* b) {
    asm volatile("mma.sync.aligned.m16n8k16.row.col.f32.bf16.bf16.f32 "
        "{%0,%1,%2,%3}, {%4,%5,%6,%7}, {%8,%9}, {%0,%1,%2,%3};"
        : "+f"(d[0]), "+f"(d[1]), "+f"(d[2]), "+f"(d[3])
        : "r"(a[0]), "r"(a[1]), "r"(a[2]), "r"(a[3]), "r"(b[0]), "r"(b[1]));
}

// fast exp on the FMA/ALU pipes (no MUFU). |rel err| < 3e-6 for x <= 0.
__device__ __forceinline__ float fexp(float x) {
    float t = fmaxf(x * 1.4426950408889634f, -125.0f);
    const float magic = 12582912.0f;              // 1.5 * 2^23
    float z = t + magic;                          // round-to-nearest int
    int   n = __float_as_int(z) - 0x4B400000;     // integer part
    float f = t - (z - magic);                    // frac in [-0.5, 0.5]
    float p = 0.00133336f;                        // Taylor of 2^f
    p = fmaf(p, f, 0.00961813f);
    p = fmaf(p, f, 0.05550411f);
    p = fmaf(p, f, 0.24022651f);
    p = fmaf(p, f, 0.69314718f);
    p = fmaf(p, f, 1.0f);
    return p * __int_as_float((n + 127) << 23);
}

// ================== mma.sync bf16-split GEMM (verified R7) =====================
#define GST 40

__device__ __forceinline__ void split_pack16(const float* f, uint4* hi, uint4* lo) {
    uint32_t uh[16], ul[16];
    #pragma unroll
    for (int j = 0; j < 16; j++) {
        const uint32_t u = __float_as_uint(f[j]);
        uh[j] = u;
        ul[j] = __float_as_uint(f[j] - __uint_as_float(u & 0xFFFF0000u));
    }
    #pragma unroll
    for (int g = 0; g < 2; g++) {
        hi[g].x = __byte_perm(uh[8*g+0], uh[8*g+1], 0x7632);
        hi[g].y = __byte_perm(uh[8*g+2], uh[8*g+3], 0x7632);
        hi[g].z = __byte_perm(uh[8*g+4], uh[8*g+5], 0x7632);
        hi[g].w = __byte_perm(uh[8*g+6], uh[8*g+7], 0x7632);
        lo[g].x = __byte_perm(ul[8*g+0], ul[8*g+1], 0x7632);
        lo[g].y = __byte_perm(ul[8*g+2], ul[8*g+3], 0x7632);
        lo[g].z = __byte_perm(ul[8*g+4], ul[8*g+5], 0x7632);
        lo[g].w = __byte_perm(ul[8*g+6], ul[8*g+7], 0x7632);
    }
}

__global__ __launch_bounds__(256) void gemm_mma(
    const float* __restrict__ Ain, const float* __restrict__ W,
    const float* __restrict__ bias, float* Cout,
    int dst_sel, int src_sel)
{
    const float* A = (src_sel == 0) ? Ain : g_ctx;
    float* C = (dst_sel == 0) ? g_q
             : (dst_sel == 1) ? g_k
             : (dst_sel == 2) ? g_v
             : Cout;

    __shared__ __align__(16) __nv_bfloat16 sAh[128 * GST];
    __shared__ __align__(16) __nv_bfloat16 sAl[128 * GST];
    __shared__ __align__(16) __nv_bfloat16 sBh[128 * GST];
    __shared__ __align__(16) __nv_bfloat16 sBl[128 * GST];

    const int tid = threadIdx.x;
    const int lane = tid & 31;
    const int wid = tid >> 5;
    const int wm = wid & 1;
    const int wn = wid >> 1;
    const int bm = blockIdx.y * 128;
    const int bn = blockIdx.x * 128;

    const int grow = tid >> 1;
    const int gcol = (tid & 1) * 16;

    const uint32_t aHiB = smem_u32(sAh), aLoB = smem_u32(sAl);
    const uint32_t bHiB = smem_u32(sBh), bLoB = smem_u32(sBl);

    const int la = lane & 15;
    const uint32_t aRowOff = (uint32_t)((wm * 64 + la) * GST + (lane >> 4) * 8) * 2;
    const uint32_t bRowOff = (uint32_t)((wn * 32 + (la & 7)) * GST + ((la >> 3) & 1) * 8) * 2;

    float acc[4][4][4];
    #pragma unroll
    for (int mt = 0; mt < 4; mt++)
        #pragma unroll
        for (int nt = 0; nt < 4; nt++)
            #pragma unroll
            for (int e = 0; e < 4; e++) acc[mt][nt][e] = 0.f;

    float aR[16], bR[16];
    {
        const float* ap = A + (size_t)(bm + grow) * DM + gcol;
        const float* bp = W + (size_t)(bn + grow) * DM + gcol;
        #pragma unroll
        for (int t = 0; t < 4; t++) {
            *reinterpret_cast<float4*>(&aR[4 * t]) = reinterpret_cast<const float4*>(ap)[t];
            *reinterpret_cast<float4*>(&bR[4 * t]) = reinterpret_cast<const float4*>(bp)[t];
        }
    }

    #pragma unroll 1
    for (int it = 0; it < DM / 32; it++) {
        {
            uint4 hi[2], lo[2];
            split_pack16(aR, hi, lo);
            const int off = grow * GST + gcol;
            *reinterpret_cast<uint4*>(&sAh[off]) = hi[0];
            *reinterpret_cast<uint4*>(&sAh[off + 8]) = hi[1];
            *reinterpret_cast<uint4*>(&sAl[off]) = lo[0];
            *reinterpret_cast<uint4*>(&sAl[off + 8]) = lo[1];
            split_pack16(bR, hi, lo);
            *reinterpret_cast<uint4*>(&sBh[off]) = hi[0];
            *reinterpret_cast<uint4*>(&sBh[off + 8]) = hi[1];
            *reinterpret_cast<uint4*>(&sBl[off]) = lo[0];
            *reinterpret_cast<uint4*>(&sBl[off + 8]) = lo[1];
        }
        __syncthreads();

        if (it + 1 < DM / 32) {
            const float* ap = A + (size_t)(bm + grow) * DM + (it + 1) * 32 + gcol;
            const float* bp = W + (size_t)(bn + grow) * DM + (it + 1) * 32 + gcol;
            #pragma unroll
            for (int t = 0; t < 4; t++) {
                *reinterpret_cast<float4*>(&aR[4 * t]) = reinterpret_cast<const float4*>(ap)[t];
                *reinterpret_cast<float4*>(&bR[4 * t]) = reinterpret_cast<const float4*>(bp)[t];
            }
        }

        #pragma unroll
        for (int kk = 0; kk < 2; kk++) {
            const uint32_t kOff = (uint32_t)(kk * 16) * 2;
            uint32_t ah[4][4], al[4][4];
            #pragma unroll
            for (int mt = 0; mt < 4; mt++) {
                const uint32_t ro = aRowOff + (uint32_t)(mt * 16 * GST) * 2 + kOff;
                ldm_x4(ah[mt], aHiB + ro);
                ldm_x4(al[mt], aLoB + ro);
            }
            #pragma unroll
            for (int nt = 0; nt < 4; nt++) {
                const uint32_t ro = bRowOff + (uint32_t)(nt * 8 * GST) * 2 + kOff;
                uint32_t bh[2], bl[2];
                ldm_x2(bh, bHiB + ro);
                ldm_x2(bl, bLoB + ro);
                #pragma unroll
                for (int mt = 0; mt < 4; mt++) {
                    mma_bf16(acc[mt][nt], ah[mt], bh);
                    mma_bf16(acc[mt][nt], ah[mt], bl);
                    mma_bf16(acc[mt][nt], al[mt], bh);
                }
            }
        }
        __syncthreads();
    }

    const int er = lane >> 2;
    const int ec = (lane & 3) * 2;
    #pragma unroll
    for (int mt = 0; mt < 4; mt++) {
        #pragma unroll
        for (int nt = 0; nt < 4; nt++) {
            const int col = bn + wn * 32 + nt * 8 + ec;
            const float b0 = bias[col], b1 = bias[col + 1];
            const int r0 = bm + wm * 64 + mt * 16 + er;
            float2 v0, v1;
            v0.x = acc[mt][nt][0] + b0; v0.y = acc[mt][nt][1] + b1;
            v1.x = acc[mt][nt][2] + b0; v1.y = acc[mt][nt][3] + b1;
            *reinterpret_cast<float2*>(&C[(size_t)r0 * DM + col]) = v0;
            *reinterpret_cast<float2*>(&C[(size_t)(r0 + 8) * DM + col]) = v1;
        }
    }
}

// ---------------- RoPE (verified; unchanged) -----------------------------------
__global__ __launch_bounds__(512) void rope_naive()
{
    const int token = blockIdx.x;
    const int pos = token & (SEQ - 1);
    const int h = threadIdx.x >> 5;
    const int i = threadIdx.x & 31;

    const float expo = (float)(2 * i) / 64.0f;
    const float invf = 1.0f / powf(10000.0f, expo);
    const float ang = (float)pos * invf;
    const float c = cosf(ang);
    const float s = sinf(ang);

    const size_t base = (size_t)token * DM + h * HD;
    float a = g_q[base + i], b = g_q[base + i + 32];
    g_q[base + i]      = a * c - b * s;
    g_q[base + i + 32] = b * c + a * s;
    a = g_k[base + i];  b = g_k[base + i + 32];
    g_k[base + i]      = a * c - b * s;
    g_k[base + i + 32] = b * c + a * s;
}

// ================== mma.sync flash attention ===================================
// CTA per (b, h, 64 q-rows). 128 threads = 4 warps; warp w owns q rows w*16..+15.
// bf16-split (3 products) for both QK^T and PV. Softmax in C-fragment registers
// with FMA-pipe fexp. P reused as A-fragment directly from registers.
#define AST 72   // bf16 smem stride (144 B: 16B-aligned, ldmatrix conflict-free)

// cooperative 64x64 fp32 tile -> hi/lo bf16 smem (128 threads, 32 floats each)
__device__ __forceinline__ void load_split_64x64(
    const float* __restrict__ src, __nv_bfloat16* dh, __nv_bfloat16* dl,
    int tid, float scale)
{
    const int row = tid >> 1;
    const int c0 = (tid & 1) * 32;
    const float* p = src + (size_t)row * DM + c0;
    float f[32];
    #pragma unroll
    for (int t = 0; t < 8; t++)
        *reinterpret_cast<float4*>(&f[4 * t]) = reinterpret_cast<const float4*>(p)[t];
    #pragma unroll
    for (int j = 0; j < 32; j++) f[j] *= scale;
    uint4 hi[2], lo[2];
    const int off = row * AST + c0;
    split_pack16(&f[0], hi, lo);
    *reinterpret_cast<uint4*>(&dh[off])     = hi[0];
    *reinterpret_cast<uint4*>(&dh[off + 8]) = hi[1];
    *reinterpret_cast<uint4*>(&dl[off])     = lo[0];
    *reinterpret_cast<uint4*>(&dl[off + 8]) = lo[1];
    split_pack16(&f[16], hi, lo);
    *reinterpret_cast<uint4*>(&dh[off + 16]) = hi[0];
    *reinterpret_cast<uint4*>(&dh[off + 24]) = hi[1];
    *reinterpret_cast<uint4*>(&dl[off + 16]) = lo[0];
    *reinterpret_cast<uint4*>(&dl[off + 24]) = lo[1];
}

__global__ __launch_bounds__(128) void attn_mma()
{
    __shared__ __align__(16) __nv_bfloat16 sKh[64 * AST];
    __shared__ __align__(16) __nv_bfloat16 sKl[64 * AST];
    __shared__ __align__(16) __nv_bfloat16 sVh[64 * AST];
    __shared__ __align__(16) __nv_bfloat16 sVl[64 * AST];

    const int tid = threadIdx.x;
    const int lane = tid & 31;
    const int w = tid >> 5;              // warp 0..3
    const int q0 = blockIdx.x * 64;
    const int h  = blockIdx.y;
    const int b  = blockIdx.z;
    const size_t base = (size_t)b * SEQ * DM + (size_t)h * HD;

    const uint32_t kHiB = smem_u32(sKh), kLoB = smem_u32(sKl);
    const uint32_t vHiB = smem_u32(sVh), vLoB = smem_u32(sVl);

    // ---- stage Q (scaled by 1/8) into sKh/sKl, extract persistent A frags ----
    load_split_64x64(&g_q[base + (size_t)q0 * DM], sKh, sKl, tid, 0.125f);
    __syncthreads();

    uint32_t qh[4][4], ql[4][4];
    {
        const uint32_t ro0 = (uint32_t)((w * 16 + (lane & 15)) * AST + (lane >> 4) * 8) * 2;
        #pragma unroll
        for (int kc = 0; kc < 4; kc++) {
            ldm_x4(qh[kc], kHiB + ro0 + (uint32_t)(kc * 16) * 2);
            ldm_x4(ql[kc], kLoB + ro0 + (uint32_t)(kc * 16) * 2);
        }
    }
    __syncthreads();   // Q frags in regs; sKh/sKl free for K tiles

    float o[8][4];
    #pragma unroll
    for (int nt = 0; nt < 8; nt++)
        #pragma unroll
        for (int e = 0; e < 4; e++) o[nt][e] = 0.f;
    float m0 = -3.0e38f, m1 = -3.0e38f, l0 = 0.f, l1 = 0.f;

    // fragment address offsets (constant)
    const uint32_t bro = (uint32_t)((lane & 7) * AST + ((lane >> 3) & 1) * 8) * 2; // QK B
    const uint32_t vro = (uint32_t)(((lane & 7) + 8 * ((lane >> 3) & 1)) * AST) * 2; // PV B (trans)

    #pragma unroll 1
    for (int kt = 0; kt < SEQ / 64; kt++) {
        load_split_64x64(&g_k[base + (size_t)(kt * 64) * DM], sKh, sKl, tid, 1.0f);
        load_split_64x64(&g_v[base + (size_t)(kt * 64) * DM], sVh, sVl, tid, 1.0f);
        __syncthreads();

        // ---- S = Q . K^T  (bf16-split, fp32 accum) ----
        float s[8][4];
        #pragma unroll
        for (int nt = 0; nt < 8; nt++)
            #pragma unroll
            for (int e = 0; e < 4; e++) s[nt][e] = 0.f;

        #pragma unroll
        for (int kc = 0; kc < 4; kc++) {
            const uint32_t kOff = (uint32_t)(kc * 16) * 2;
            #pragma unroll
            for (int nt = 0; nt < 8; nt++) {
                const uint32_t ro = bro + (uint32_t)(nt * 8 * AST) * 2 + kOff;
                uint32_t bh[2], bl[2];
                ldm_x2(bh, kHiB + ro);
                ldm_x2(bl, kLoB + ro);
                mma_bf16(s[nt], qh[kc], bh);
                mma_bf16(s[nt], qh[kc], bl);
                mma_bf16(s[nt], ql[kc], bh);
            }
        }

        // ---- online softmax in fragments (rows: g=lane>>2 and g+8) ----
        float tm0 = -3.0e38f, tm1 = -3.0e38f;
        #pragma unroll
        for (int nt = 0; nt < 8; nt++) {
            tm0 = fmaxf(tm0, fmaxf(s[nt][0], s[nt][1]));
            tm1 = fmaxf(tm1, fmaxf(s[nt][2], s[nt][3]));
        }
        #pragma unroll
        for (int off = 1; off < 4; off <<= 1) {
            tm0 = fmaxf(tm0, __shfl_xor_sync(0xffffffffu, tm0, off));
            tm1 = fmaxf(tm1, __shfl_xor_sync(0xffffffffu, tm1, off));
        }
        const float nm0 = fmaxf(m0, tm0), nm1 = fmaxf(m1, tm1);
        const float corr0 = fexp(m0 - nm0), corr1 = fexp(m1 - nm1);
        float rs0 = 0.f, rs1 = 0.f;
        #pragma unroll
        for (int nt = 0; nt < 8; nt++) {
            s[nt][0] = fexp(s[nt][0] - nm0);
            s[nt][1] = fexp(s[nt][1] - nm0);
            s[nt][2] = fexp(s[nt][2] - nm1);
            s[nt][3] = fexp(s[nt][3] - nm1);
            rs0 += s[nt][0] + s[nt][1];
            rs1 += s[nt][2] + s[nt][3];
        }
        #pragma unroll
        for (int off = 1; off < 4; off <<= 1) {
            rs0 += __shfl_xor_sync(0xffffffffu, rs0, off);
            rs1 += __shfl_xor_sync(0xffffffffu, rs1, off);
        }
        l0 = l0 * corr0 + rs0;  m0 = nm0;
        l1 = l1 * corr1 + rs1;  m1 = nm1;
        #pragma unroll
        for (int nt = 0; nt < 8; nt++) {
            o[nt][0] *= corr0; o[nt][1] *= corr0;
            o[nt][2] *= corr1; o[nt][3] *= corr1;
        }

        // ---- pack P into A fragments (hi/lo split, registers only) ----
        uint32_t ph[4][4], pl[4][4];
        #pragma unroll
        for (int j = 0; j < 4; j++) {
            const int ta = 2 * j, tb = 2 * j + 1;
            uint32_t u[8], r[8];
            const float* sv[8] = {&s[ta][0], &s[ta][1], &s[ta][2], &s[ta][3],
                                  &s[tb][0], &s[tb][1], &s[tb][2], &s[tb][3]};
            #pragma unroll
            for (int e = 0; e < 8; e++) {
                const float x = *sv[e];
                u[e] = __float_as_uint(x);
                r[e] = __float_as_uint(x - __uint_as_float(u[e] & 0xFFFF0000u));
            }
            ph[j][0] = __byte_perm(u[0], u[1], 0x7632);
            ph[j][1] = __byte_perm(u[2], u[3], 0x7632);
            ph[j][2] = __byte_perm(u[4], u[5], 0x7632);
            ph[j][3] = __byte_perm(u[6], u[7], 0x7632);
            pl[j][0] = __byte_perm(r[0], r[1], 0x7632);
            pl[j][1] = __byte_perm(r[2], r[3], 0x7632);
            pl[j][2] = __byte_perm(r[4], r[5], 0x7632);
            pl[j][3] = __byte_perm(r[6], r[7], 0x7632);
        }

        // ---- O += P . V  (V via ldmatrix.trans; bf16-split) ----
        #pragma unroll
        for (int j = 0; j < 4; j++) {
            const uint32_t jOff = (uint32_t)(j * 16 * AST) * 2;
            #pragma unroll
            for (int nt = 0; nt < 8; nt++) {
                const uint32_t ro = vro + jOff + (uint32_t)(nt * 8) * 2;
                uint32_t bh[2], bl[2];
                ldm_x2t(bh, vHiB + ro);
                ldm_x2t(bl, vLoB + ro);
                mma_bf16(o[nt], ph[j], bh);
                mma_bf16(o[nt], ph[j], bl);
                mma_bf16(o[nt], pl[j], bh);
            }
        }
        __syncthreads();   // done reading tiles before next iteration overwrites
    }

    // ---- epilogue: normalize, store ctx ----
    const float i0 = 1.0f / l0, i1 = 1.0f / l1;
    const int er = lane >> 2;
    const int ec = (lane & 3) * 2;
    #pragma unroll
    for (int nt = 0; nt < 8; nt++) {
        const int col = h * HD + nt * 8 + ec;
        const int r0 = q0 + w * 16 + er;
        float2 v0, v1;
        v0.x = o[nt][0] * i0; v0.y = o[nt][1] * i0;
        v1.x = o[nt][2] * i1; v1.y = o[nt][3] * i1;
        *reinterpret_cast<float2*>(&g_ctx[(size_t)(b * SEQ + r0) * DM + col]) = v0;
        *reinterpret_cast<float2*>(&g_ctx[(size_t)(b * SEQ + r0 + 8) * DM + col]) = v1;
    }
}

// ---------------- launch -------------------------------------------------------
extern "C" void kernel_launch(void* const* d_in, const int* in_sizes, int n_in,
                              void* d_out, int out_size)
{
    const float* act[3] = {0, 0, 0};
    const float* wgt[4] = {0, 0, 0, 0};
    const float* bia[4] = {0, 0, 0, 0};
    int na = 0, nw = 0, nb = 0;
    for (int i = 0; i < n_in; i++) {
        const int s = in_sizes[i];
        if (s == NTOK * DM)      { if (na < 3) act[na++] = (const float*)d_in[i]; }
        else if (s == DM * DM)   { if (nw < 4) wgt[nw++] = (const float*)d_in[i]; }
        else if (s == DM)        { if (nb < 4) bia[nb++] = (const float*)d_in[i]; }
    }
    const float* query = act[0];
    const float* key   = act[1];
    const float* value = act[2];
    const float* Wq = wgt[0]; const float* Wk = wgt[1];
    const float* Wv = wgt[2]; const float* Wo = wgt[3];
    const float* bq = bia[0]; const float* bk = bia[1];
    const float* bv = bia[2]; const float* bo = bia[3];
    float* out = (float*)d_out;

    const dim3 ggrid(DM / 128, NTOK / 128);   // (8, 64)

    // QKV projections -> g_q, g_k, g_v
    gemm_mma<<<ggrid, 256>>>(query, Wq, bq, out, 0, 0);
    gemm_mma<<<ggrid, 256>>>(key,   Wk, bk, out, 1, 0);
    gemm_mma<<<ggrid, 256>>>(value, Wv, bv, out, 2, 0);

    // RoPE in place on g_q, g_k
    rope_naive<<<NTOK, 512>>>();

    // mma flash attention -> g_ctx
    attn_mma<<<dim3(SEQ / 64, NH, BATCH), 128>>>();

    // output projection: g_ctx @ Wo^T + bo -> out
    gemm_mma<<<ggrid, 256>>>(query, Wo, bo, out, 3, 1);
}

// round 9
// speedup vs baseline: 22.1977x; 1.0097x over previous
#include <cuda_runtime.h>
#include <cuda_bf16.h>
#include <stdint.h>
#include <math.h>

// Problem constants
#define BATCH 16
#define SEQ 512
#define DM 1024
#define NH 16
#define HD 64
#define NTOK (BATCH * SEQ)   // 8192

// ---------------- scratch (allocation-free: __device__ globals) ----------------
__device__ float g_q[NTOK * DM];
__device__ float g_k[NTOK * DM];
__device__ float g_v[NTOK * DM];
__device__ float g_ctx[NTOK * DM];
// pre-split weights (4 matrices, bf16 hi/lo)
__device__ __nv_bfloat16 g_wh[4u * DM * DM];
__device__ __nv_bfloat16 g_wl[4u * DM * DM];

// ---------------- warp-level tensor core primitives (sm_80+, no 'a' target) ----
__device__ __forceinline__ uint32_t smem_u32(const void* p) {
    uint32_t a;
    asm("{ .reg .u64 t; cvta.to.shared.u64 t, %1; cvt.u32.u64 %0, t; }"
        : "=r"(a) : "l"(p));
    return a;
}
__device__ __forceinline__ void ldm_x4(uint32_t* r, uint32_t addr) {
    asm volatile("ldmatrix.sync.aligned.m8n8.x4.shared.b16 {%0,%1,%2,%3}, [%4];"
        : "=r"(r[0]), "=r"(r[1]), "=r"(r[2]), "=r"(r[3]) : "r"(addr));
}
__device__ __forceinline__ void ldm_x2(uint32_t* r, uint32_t addr) {
    asm volatile("ldmatrix.sync.aligned.m8n8.x2.shared.b16 {%0,%1}, [%2];"
        : "=r"(r[0]), "=r"(r[1]) : "r"(addr));
}
__device__ __forceinline__ void ldm_x2t(uint32_t* r, uint32_t addr) {
    asm volatile("ldmatrix.sync.aligned.m8n8.x2.trans.shared.b16 {%0,%1}, [%2];"
        : "=r"(r[0]), "=r"(r[1]) : "r"(addr));
}
__device__ __forceinline__ void mma_bf16(float* d, const uint32_t* a, const uint32_t* b) {
    asm volatile("mma.sync.aligned.m16n8k16.row.col.f32.bf16.bf16.f32 "
        "{%0,%1,%2,%3}, {%4,%5,%6,%7}, {%8,%9}, {%0,%1,%2,%3};"
        : "+f"(d[0]), "+f"(d[1]), "+f"(d[2]), "+f"(d[3])
        : "r"(a[0]), "r"(a[1]), "r"(a[2]), "r"(a[3]), "r"(b[0]), "r"(b[1]));
}

// fast exp on the FMA/ALU pipes (no MUFU). |rel err| < 3e-6 for x <= 0.
__device__ __forceinline__ float fexp(float x) {
    float t = fmaxf(x * 1.4426950408889634f, -125.0f);
    const float magic = 12582912.0f;              // 1.5 * 2^23
    float z = t + magic;
    int   n = __float_as_int(z) - 0x4B400000;
    float f = t - (z - magic);
    float p = 0.00133336f;
    p = fmaf(p, f, 0.00961813f);
    p = fmaf(p, f, 0.05550411f);
    p = fmaf(p, f, 0.24022651f);
    p = fmaf(p, f, 0.69314718f);
    p = fmaf(p, f, 1.0f);
    return p * __int_as_float((n + 127) << 23);
}

// ---------------- weight pre-split: fp32 -> bf16 hi/lo -------------------------
// hi = truncate-to-bf16(x) (top 16 bits), lo = truncate-to-bf16(x - hi).
// Same math as split_pack16 -> bit-identical GEMM results.
__global__ __launch_bounds__(256) void split_w_all(
    const float* __restrict__ W0, const float* __restrict__ W1,
    const float* __restrict__ W2, const float* __restrict__ W3)
{
    const float* W = (blockIdx.y == 0) ? W0
                   : (blockIdx.y == 1) ? W1
                   : (blockIdx.y == 2) ? W2 : W3;
    const size_t dst0 = (size_t)blockIdx.y * DM * DM;
    const size_t i = ((size_t)blockIdx.x * 256 + threadIdx.x) * 4;

    const float4 v = *reinterpret_cast<const float4*>(W + i);
    const float f[4] = {v.x, v.y, v.z, v.w};
    uint32_t u[4], r[4];
    #pragma unroll
    for (int j = 0; j < 4; j++) {
        u[j] = __float_as_uint(f[j]);
        r[j] = __float_as_uint(f[j] - __uint_as_float(u[j] & 0xFFFF0000u));
    }
    uint2 hi, lo;
    hi.x = __byte_perm(u[0], u[1], 0x7632); hi.y = __byte_perm(u[2], u[3], 0x7632);
    lo.x = __byte_perm(r[0], r[1], 0x7632); lo.y = __byte_perm(r[2], r[3], 0x7632);
    *reinterpret_cast<uint2*>(&g_wh[dst0 + i]) = hi;
    *reinterpret_cast<uint2*>(&g_wl[dst0 + i]) = lo;
}

// ================== mma.sync bf16-split GEMM ===================================
// C[m,n] = sum_k A[m,k] * W[n,k] + bias[n]; W consumed pre-split from g_wh/g_wl.
#define GST 40

__device__ __forceinline__ void split_pack16(const float* f, uint4* hi, uint4* lo) {
    uint32_t uh[16], ul[16];
    #pragma unroll
    for (int j = 0; j < 16; j++) {
        const uint32_t u = __float_as_uint(f[j]);
        uh[j] = u;
        ul[j] = __float_as_uint(f[j] - __uint_as_float(u & 0xFFFF0000u));
    }
    #pragma unroll
    for (int g = 0; g < 2; g++) {
        hi[g].x = __byte_perm(uh[8*g+0], uh[8*g+1], 0x7632);
        hi[g].y = __byte_perm(uh[8*g+2], uh[8*g+3], 0x7632);
        hi[g].z = __byte_perm(uh[8*g+4], uh[8*g+5], 0x7632);
        hi[g].w = __byte_perm(uh[8*g+6], uh[8*g+7], 0x7632);
        lo[g].x = __byte_perm(ul[8*g+0], ul[8*g+1], 0x7632);
        lo[g].y = __byte_perm(ul[8*g+2], ul[8*g+3], 0x7632);
        lo[g].z = __byte_perm(ul[8*g+4], ul[8*g+5], 0x7632);
        lo[g].w = __byte_perm(ul[8*g+6], ul[8*g+7], 0x7632);
    }
}

// dst_sel: 0->g_q, 1->g_k, 2->g_v, 3->Cout;  src_sel: 0->Ain, 1->g_ctx
// w_sel: which pre-split weight matrix (0..3)
__global__ __launch_bounds__(256) void gemm_mma(
    const float* __restrict__ Ain, const float* __restrict__ bias, float* Cout,
    int dst_sel, int src_sel, int w_sel)
{
    const float* A = (src_sel == 0) ? Ain : g_ctx;
    float* C = (dst_sel == 0) ? g_q
             : (dst_sel == 1) ? g_k
             : (dst_sel == 2) ? g_v
             : Cout;
    const __nv_bfloat16* wh = g_wh + (size_t)w_sel * DM * DM;
    const __nv_bfloat16* wl = g_wl + (size_t)w_sel * DM * DM;

    __shared__ __align__(16) __nv_bfloat16 sAh[128 * GST];
    __shared__ __align__(16) __nv_bfloat16 sAl[128 * GST];
    __shared__ __align__(16) __nv_bfloat16 sBh[128 * GST];
    __shared__ __align__(16) __nv_bfloat16 sBl[128 * GST];

    const int tid = threadIdx.x;
    const int lane = tid & 31;
    const int wid = tid >> 5;
    const int wm = wid & 1;
    const int wn = wid >> 1;
    const int bm = blockIdx.y * 128;
    const int bn = blockIdx.x * 128;

    const int grow = tid >> 1;           // 0..127
    const int gcol = (tid & 1) * 16;     // fp32 A: 16 floats; bf16 B: 16 elems

    const uint32_t aHiB = smem_u32(sAh), aLoB = smem_u32(sAl);
    const uint32_t bHiB = smem_u32(sBh), bLoB = smem_u32(sBl);

    const int la = lane & 15;
    const uint32_t aRowOff = (uint32_t)((wm * 64 + la) * GST + (lane >> 4) * 8) * 2;
    const uint32_t bRowOff = (uint32_t)((wn * 32 + (la & 7)) * GST + ((la >> 3) & 1) * 8) * 2;

    float acc[4][4][4];
    #pragma unroll
    for (int mt = 0; mt < 4; mt++)
        #pragma unroll
        for (int nt = 0; nt < 4; nt++)
            #pragma unroll
            for (int e = 0; e < 4; e++) acc[mt][nt][e] = 0.f;

    // prefetch chunk 0
    float aR[16];
    uint4 bhR[2], blR[2];
    {
        const float* ap = A + (size_t)(bm + grow) * DM + gcol;
        #pragma unroll
        for (int t = 0; t < 4; t++)
            *reinterpret_cast<float4*>(&aR[4 * t]) = reinterpret_cast<const float4*>(ap)[t];
        const __nv_bfloat16* bhp = wh + (size_t)(bn + grow) * DM + gcol;
        const __nv_bfloat16* blp = wl + (size_t)(bn + grow) * DM + gcol;
        bhR[0] = reinterpret_cast<const uint4*>(bhp)[0];
        bhR[1] = reinterpret_cast<const uint4*>(bhp + 8)[0];
        blR[0] = reinterpret_cast<const uint4*>(blp)[0];
        blR[1] = reinterpret_cast<const uint4*>(blp + 8)[0];
    }

    #pragma unroll 1
    for (int it = 0; it < DM / 32; it++) {
        // store prefetched chunk
        {
            uint4 hi[2], lo[2];
            split_pack16(aR, hi, lo);
            const int off = grow * GST + gcol;
            *reinterpret_cast<uint4*>(&sAh[off])     = hi[0];
            *reinterpret_cast<uint4*>(&sAh[off + 8]) = hi[1];
            *reinterpret_cast<uint4*>(&sAl[off])     = lo[0];
            *reinterpret_cast<uint4*>(&sAl[off + 8]) = lo[1];
            *reinterpret_cast<uint4*>(&sBh[off])     = bhR[0];
            *reinterpret_cast<uint4*>(&sBh[off + 8]) = bhR[1];
            *reinterpret_cast<uint4*>(&sBl[off])     = blR[0];
            *reinterpret_cast<uint4*>(&sBl[off + 8]) = blR[1];
        }
        __syncthreads();

        // prefetch next chunk (overlaps with MMA burst)
        if (it + 1 < DM / 32) {
            const float* ap = A + (size_t)(bm + grow) * DM + (it + 1) * 32 + gcol;
            #pragma unroll
            for (int t = 0; t < 4; t++)
                *reinterpret_cast<float4*>(&aR[4 * t]) = reinterpret_cast<const float4*>(ap)[t];
            const __nv_bfloat16* bhp = wh + (size_t)(bn + grow) * DM + (it + 1) * 32 + gcol;
            const __nv_bfloat16* blp = wl + (size_t)(bn + grow) * DM + (it + 1) * 32 + gcol;
            bhR[0] = reinterpret_cast<const uint4*>(bhp)[0];
            bhR[1] = reinterpret_cast<const uint4*>(bhp + 8)[0];
            blR[0] = reinterpret_cast<const uint4*>(blp)[0];
            blR[1] = reinterpret_cast<const uint4*>(blp + 8)[0];
        }

        #pragma unroll
        for (int kk = 0; kk < 2; kk++) {
            const uint32_t kOff = (uint32_t)(kk * 16) * 2;
            uint32_t ah[4][4], al[4][4];
            #pragma unroll
            for (int mt = 0; mt < 4; mt++) {
                const uint32_t ro = aRowOff + (uint32_t)(mt * 16 * GST) * 2 + kOff;
                ldm_x4(ah[mt], aHiB + ro);
                ldm_x4(al[mt], aLoB + ro);
            }
            #pragma unroll
            for (int nt = 0; nt < 4; nt++) {
                const uint32_t ro = bRowOff + (uint32_t)(nt * 8 * GST) * 2 + kOff;
                uint32_t bh[2], bl[2];
                ldm_x2(bh, bHiB + ro);
                ldm_x2(bl, bLoB + ro);
                #pragma unroll
                for (int mt = 0; mt < 4; mt++) {
                    mma_bf16(acc[mt][nt], ah[mt], bh);
                    mma_bf16(acc[mt][nt], ah[mt], bl);
                    mma_bf16(acc[mt][nt], al[mt], bh);
                }
            }
        }
        __syncthreads();
    }

    const int er = lane >> 2;
    const int ec = (lane & 3) * 2;
    #pragma unroll
    for (int mt = 0; mt < 4; mt++) {
        #pragma unroll
        for (int nt = 0; nt < 4; nt++) {
            const int col = bn + wn * 32 + nt * 8 + ec;
            const float b0 = bias[col], b1 = bias[col + 1];
            const int r0 = bm + wm * 64 + mt * 16 + er;
            float2 v0, v1;
            v0.x = acc[mt][nt][0] + b0; v0.y = acc[mt][nt][1] + b1;
            v1.x = acc[mt][nt][2] + b0; v1.y = acc[mt][nt][3] + b1;
            *reinterpret_cast<float2*>(&C[(size_t)r0 * DM + col]) = v0;
            *reinterpret_cast<float2*>(&C[(size_t)(r0 + 8) * DM + col]) = v1;
        }
    }
}

// ---------------- RoPE (verified; unchanged) -----------------------------------
__global__ __launch_bounds__(512) void rope_naive()
{
    const int token = blockIdx.x;
    const int pos = token & (SEQ - 1);
    const int h = threadIdx.x >> 5;
    const int i = threadIdx.x & 31;

    const float expo = (float)(2 * i) / 64.0f;
    const float invf = 1.0f / powf(10000.0f, expo);
    const float ang = (float)pos * invf;
    const float c = cosf(ang);
    const float s = sinf(ang);

    const size_t base = (size_t)token * DM + h * HD;
    float a = g_q[base + i], b = g_q[base + i + 32];
    g_q[base + i]      = a * c - b * s;
    g_q[base + i + 32] = b * c + a * s;
    a = g_k[base + i];  b = g_k[base + i + 32];
    g_k[base + i]      = a * c - b * s;
    g_k[base + i + 32] = b * c + a * s;
}

// ================== mma.sync flash attention (verified R8; unchanged) ==========
#define AST 72

__device__ __forceinline__ void load_split_64x64(
    const float* __restrict__ src, __nv_bfloat16* dh, __nv_bfloat16* dl,
    int tid, float scale)
{
    const int row = tid >> 1;
    const int c0 = (tid & 1) * 32;
    const float* p = src + (size_t)row * DM + c0;
    float f[32];
    #pragma unroll
    for (int t = 0; t < 8; t++)
        *reinterpret_cast<float4*>(&f[4 * t]) = reinterpret_cast<const float4*>(p)[t];
    #pragma unroll
    for (int j = 0; j < 32; j++) f[j] *= scale;
    uint4 hi[2], lo[2];
    const int off = row * AST + c0;
    split_pack16(&f[0], hi, lo);
    *reinterpret_cast<uint4*>(&dh[off])     = hi[0];
    *reinterpret_cast<uint4*>(&dh[off + 8]) = hi[1];
    *reinterpret_cast<uint4*>(&dl[off])     = lo[0];
    *reinterpret_cast<uint4*>(&dl[off + 8]) = lo[1];
    split_pack16(&f[16], hi, lo);
    *reinterpret_cast<uint4*>(&dh[off + 16]) = hi[0];
    *reinterpret_cast<uint4*>(&dh[off + 24]) = hi[1];
    *reinterpret_cast<uint4*>(&dl[off + 16]) = lo[0];
    *reinterpret_cast<uint4*>(&dl[off + 24]) = lo[1];
}

__global__ __launch_bounds__(128) void attn_mma()
{
    __shared__ __align__(16) __nv_bfloat16 sKh[64 * AST];
    __shared__ __align__(16) __nv_bfloat16 sKl[64 * AST];
    __shared__ __align__(16) __nv_bfloat16 sVh[64 * AST];
    __shared__ __align__(16) __nv_bfloat16 sVl[64 * AST];

    const int tid = threadIdx.x;
    const int lane = tid & 31;
    const int w = tid >> 5;
    const int q0 = blockIdx.x * 64;
    const int h  = blockIdx.y;
    const int b  = blockIdx.z;
    const size_t base = (size_t)b * SEQ * DM + (size_t)h * HD;

    const uint32_t kHiB = smem_u32(sKh), kLoB = smem_u32(sKl);
    const uint32_t vHiB = smem_u32(sVh), vLoB = smem_u32(sVl);

    load_split_64x64(&g_q[base + (size_t)q0 * DM], sKh, sKl, tid, 0.125f);
    __syncthreads();

    uint32_t qh[4][4], ql[4][4];
    {
        const uint32_t ro0 = (uint32_t)((w * 16 + (lane & 15)) * AST + (lane >> 4) * 8) * 2;
        #pragma unroll
        for (int kc = 0; kc < 4; kc++) {
            ldm_x4(qh[kc], kHiB + ro0 + (uint32_t)(kc * 16) * 2);
            ldm_x4(ql[kc], kLoB + ro0 + (uint32_t)(kc * 16) * 2);
        }
    }
    __syncthreads();

    float o[8][4];
    #pragma unroll
    for (int nt = 0; nt < 8; nt++)
        #pragma unroll
        for (int e = 0; e < 4; e++) o[nt][e] = 0.f;
    float m0 = -3.0e38f, m1 = -3.0e38f, l0 = 0.f, l1 = 0.f;

    const uint32_t bro = (uint32_t)((lane & 7) * AST + ((lane >> 3) & 1) * 8) * 2;
    const uint32_t vro = (uint32_t)(((lane & 7) + 8 * ((lane >> 3) & 1)) * AST) * 2;

    #pragma unroll 1
    for (int kt = 0; kt < SEQ / 64; kt++) {
        load_split_64x64(&g_k[base + (size_t)(kt * 64) * DM], sKh, sKl, tid, 1.0f);
        load_split_64x64(&g_v[base + (size_t)(kt * 64) * DM], sVh, sVl, tid, 1.0f);
        __syncthreads();

        float s[8][4];
        #pragma unroll
        for (int nt = 0; nt < 8; nt++)
            #pragma unroll
            for (int e = 0; e < 4; e++) s[nt][e] = 0.f;

        #pragma unroll
        for (int kc = 0; kc < 4; kc++) {
            const uint32_t kOff = (uint32_t)(kc * 16) * 2;
            #pragma unroll
            for (int nt = 0; nt < 8; nt++) {
                const uint32_t ro = bro + (uint32_t)(nt * 8 * AST) * 2 + kOff;
                uint32_t bh[2], bl[2];
                ldm_x2(bh, kHiB + ro);
                ldm_x2(bl, kLoB + ro);
                mma_bf16(s[nt], qh[kc], bh);
                mma_bf16(s[nt], qh[kc], bl);
                mma_bf16(s[nt], ql[kc], bh);
            }
        }

        float tm0 = -3.0e38f, tm1 = -3.0e38f;
        #pragma unroll
        for (int nt = 0; nt < 8; nt++) {
            tm0 = fmaxf(tm0, fmaxf(s[nt][0], s[nt][1]));
            tm1 = fmaxf(tm1, fmaxf(s[nt][2], s[nt][3]));
        }
        #pragma unroll
        for (int off = 1; off < 4; off <<= 1) {
            tm0 = fmaxf(tm0, __shfl_xor_sync(0xffffffffu, tm0, off));
            tm1 = fmaxf(tm1, __shfl_xor_sync(0xffffffffu, tm1, off));
        }
        const float nm0 = fmaxf(m0, tm0), nm1 = fmaxf(m1, tm1);
        const float corr0 = fexp(m0 - nm0), corr1 = fexp(m1 - nm1);
        float rs0 = 0.f, rs1 = 0.f;
        #pragma unroll
        for (int nt = 0; nt < 8; nt++) {
            s[nt][0] = fexp(s[nt][0] - nm0);
            s[nt][1] = fexp(s[nt][1] - nm0);
            s[nt][2] = fexp(s[nt][2] - nm1);
            s[nt][3] = fexp(s[nt][3] - nm1);
            rs0 += s[nt][0] + s[nt][1];
            rs1 += s[nt][2] + s[nt][3];
        }
        #pragma unroll
        for (int off = 1; off < 4; off <<= 1) {
            rs0 += __shfl_xor_sync(0xffffffffu, rs0, off);
            rs1 += __shfl_xor_sync(0xffffffffu, rs1, off);
        }
        l0 = l0 * corr0 + rs0;  m0 = nm0;
        l1 = l1 * corr1 + rs1;  m1 = nm1;
        #pragma unroll
        for (int nt = 0; nt < 8; nt++) {
            o[nt][0] *= corr0; o[nt][1] *= corr0;
            o[nt][2] *= corr1; o[nt][3] *= corr1;
        }

        uint32_t ph[4][4], pl[4][4];
        #pragma unroll
        for (int j = 0; j < 4; j++) {
            const int ta = 2 * j, tb = 2 * j + 1;
            uint32_t u[8], r[8];
            const float* sv[8] = {&s[ta][0], &s[ta][1], &s[ta][2], &s[ta][3],
                                  &s[tb][0], &s[tb][1], &s[tb][2], &s[tb][3]};
            #pragma unroll
            for (int e = 0; e < 8; e++) {
                const float x = *sv[e];
                u[e] = __float_as_uint(x);
                r[e] = __float_as_uint(x - __uint_as_float(u[e] & 0xFFFF0000u));
            }
            ph[j][0] = __byte_perm(u[0], u[1], 0x7632);
            ph[j][1] = __byte_perm(u[2], u[3], 0x7632);
            ph[j][2] = __byte_perm(u[4], u[5], 0x7632);
            ph[j][3] = __byte_perm(u[6], u[7], 0x7632);
            pl[j][0] = __byte_perm(r[0], r[1], 0x7632);
            pl[j][1] = __byte_perm(r[2], r[3], 0x7632);
            pl[j][2] = __byte_perm(r[4], r[5], 0x7632);
            pl[j][3] = __byte_perm(r[6], r[7], 0x7632);
        }

        #pragma unroll
        for (int j = 0; j < 4; j++) {
            const uint32_t jOff = (uint32_t)(j * 16 * AST) * 2;
            #pragma unroll
            for (int nt = 0; nt < 8; nt++) {
                const uint32_t ro = vro + jOff + (uint32_t)(nt * 8) * 2;
                uint32_t bh[2], bl[2];
                ldm_x2t(bh, vHiB + ro);
                ldm_x2t(bl, vLoB + ro);
                mma_bf16(o[nt], ph[j], bh);
                mma_bf16(o[nt], ph[j], bl);
                mma_bf16(o[nt], pl[j], bh);
            }
        }
        __syncthreads();
    }

    const float i0 = 1.0f / l0, i1 = 1.0f / l1;
    const int er = lane >> 2;
    const int ec = (lane & 3) * 2;
    #pragma unroll
    for (int nt = 0; nt < 8; nt++) {
        const int col = h * HD + nt * 8 + ec;
        const int r0 = q0 + w * 16 + er;
        float2 v0, v1;
        v0.x = o[nt][0] * i0; v0.y = o[nt][1] * i0;
        v1.x = o[nt][2] * i1; v1.y = o[nt][3] * i1;
        *reinterpret_cast<float2*>(&g_ctx[(size_t)(b * SEQ + r0) * DM + col]) = v0;
        *reinterpret_cast<float2*>(&g_ctx[(size_t)(b * SEQ + r0 + 8) * DM + col]) = v1;
    }
}

// ---------------- launch -------------------------------------------------------
extern "C" void kernel_launch(void* const* d_in, const int* in_sizes, int n_in,
                              void* d_out, int out_size)
{
    const float* act[3] = {0, 0, 0};
    const float* wgt[4] = {0, 0, 0, 0};
    const float* bia[4] = {0, 0, 0, 0};
    int na = 0, nw = 0, nb = 0;
    for (int i = 0; i < n_in; i++) {
        const int s = in_sizes[i];
        if (s == NTOK * DM)      { if (na < 3) act[na++] = (const float*)d_in[i]; }
        else if (s == DM * DM)   { if (nw < 4) wgt[nw++] = (const float*)d_in[i]; }
        else if (s == DM)        { if (nb < 4) bia[nb++] = (const float*)d_in[i]; }
    }
    const float* query = act[0];
    const float* key   = act[1];
    const float* value = act[2];
    const float* Wq = wgt[0]; const float* Wk = wgt[1];
    const float* Wv = wgt[2]; const float* Wo = wgt[3];
    const float* bq = bia[0]; const float* bk = bia[1];
    const float* bv = bia[2]; const float* bo = bia[3];
    float* out = (float*)d_out;

    // pre-split weights -> g_wh/g_wl (order: Wq, Wk, Wv, Wo)
    split_w_all<<<dim3(DM * DM / 4 / 256, 4), 256>>>(Wq, Wk, Wv, Wo);

    const dim3 ggrid(DM / 128, NTOK / 128);   // (8, 64)

    // QKV projections -> g_q, g_k, g_v
    gemm_mma<<<ggrid, 256>>>(query, bq, out, 0, 0, 0);
    gemm_mma<<<ggrid, 256>>>(key,   bk, out, 1, 0, 1);
    gemm_mma<<<ggrid, 256>>>(value, bv, out, 2, 0, 2);

    // RoPE in place on g_q, g_k
    rope_naive<<<NTOK, 512>>>();

    // mma flash attention -> g_ctx
    attn_mma<<<dim3(SEQ / 64, NH, BATCH), 128>>>();

    // output projection: g_ctx @ Wo^T + bo -> out
    gemm_mma<<<ggrid, 256>>>(query, bo, out, 3, 1, 3);
}